// round 15
// baseline (speedup 1.0000x reference)
#include <cuda_runtime.h>
#include <cuda_bf16.h>
#include <cstdint>

#define HEADS 12
#define NTOK  1024
#define HD    64
#define DIM   768
#define BHT   96
#define MTOT  8192

__device__ __align__(16) __nv_bfloat16 g_xh[MTOT*DIM],  g_xl[MTOT*DIM];
__device__ __align__(16) __nv_bfloat16 g_wh[2304*DIM],  g_wl[2304*DIM];
__device__ __align__(16) __nv_bfloat16 g_pwh[DIM*DIM],  g_pwl[DIM*DIM];
__device__ __align__(16) __nv_bfloat16 g_qh[BHT*NTOK*HD], g_ql[BHT*NTOK*HD];
__device__ __align__(16) __nv_bfloat16 g_kh[BHT*NTOK*HD], g_kl[BHT*NTOK*HD];
__device__ __align__(16) __nv_bfloat16 g_vth[BHT*HD*NTOK], g_vtl[BHT*HD*NTOK];
__device__ __align__(16) __nv_bfloat16 g_ah[MTOT*DIM],  g_al[MTOT*DIM];
__device__ float g_relh[BHT*NTOK*32];
__device__ float g_relw[BHT*NTOK*32];

__device__ __forceinline__ void mma16816(float* c, const unsigned* a, const unsigned* b) {
  asm volatile(
    "mma.sync.aligned.m16n8k16.row.col.f32.bf16.bf16.f32 "
    "{%0,%1,%2,%3}, {%4,%5,%6,%7}, {%8,%9}, {%0,%1,%2,%3};\n"
    : "+f"(c[0]), "+f"(c[1]), "+f"(c[2]), "+f"(c[3])
    : "r"(a[0]), "r"(a[1]), "r"(a[2]), "r"(a[3]), "r"(b[0]), "r"(b[1]));
}
__device__ __forceinline__ unsigned pack2(float a, float b) {
  __nv_bfloat162 t = __floats2bfloat162_rn(a, b);
  return *reinterpret_cast<unsigned*>(&t);
}
__device__ __forceinline__ float bf16hi(float v) {
  return __bfloat162float(__float2bfloat16(v));
}
__device__ __forceinline__ uint32_t s2u(const void* p) {
  uint32_t a;
  asm("{ .reg .u64 t; cvta.to.shared.u64 t, %1; cvt.u32.u64 %0, t; }" : "=r"(a) : "l"(p));
  return a;
}
#define LDSM4(r, a) \
  asm volatile("ldmatrix.sync.aligned.m8n8.x4.shared.b16 {%0,%1,%2,%3},[%4];" \
    : "=r"((r)[0]), "=r"((r)[1]), "=r"((r)[2]), "=r"((r)[3]) : "r"(a))
#define CP16(s, g) \
  asm volatile("cp.async.cg.shared.global [%0],[%1],16;" :: "r"(s), "l"(g))
#define CP_COMMIT asm volatile("cp.async.commit_group;" ::: "memory")
#define CP_WAIT1  asm volatile("cp.async.wait_group 1;" ::: "memory")
#define CP_WAIT0  asm volatile("cp.async.wait_group 0;" ::: "memory")

#define NX (MTOT*DIM)
#define NW (2304*DIM)
#define NP (DIM*DIM)

// merged fp32 -> bf16 hi/lo split for x, qkv_w, proj_w in one launch
__global__ void split_all_kernel(const float* __restrict__ x,
                                 const float* __restrict__ w,
                                 const float* __restrict__ pw) {
  int i = blockIdx.x * 256 + threadIdx.x;
  const float* src;
  __nv_bfloat16 *h, *l;
  int j;
  if (i < NX)           { src = x;  h = g_xh;  l = g_xl;  j = i; }
  else if (i < NX+NW)   { src = w;  h = g_wh;  l = g_wl;  j = i - NX; }
  else if (i < NX+NW+NP){ src = pw; h = g_pwh; l = g_pwl; j = i - NX - NW; }
  else return;
  float v = src[j];
  __nv_bfloat16 hb = __float2bfloat16(v);
  h[j] = hb;
  l[j] = __float2bfloat16(v - __bfloat162float(hb));
}

// GEMM: tile 128x64, 3-stage cp.async, 24 K-chunks of 32; prefetch hoisted
// to top of chunk (full-epoch coverage for c+2).
template<int EPI>
__global__ __launch_bounds__(256, 2) void gemm3bf16(const float* __restrict__ bias,
                                                    float* __restrict__ out) {
  extern __shared__ __align__(16) unsigned dynsm[];
  const int tid = threadIdx.x, lane = tid & 31, warp = tid >> 5;
  const int wm = warp >> 1, wn = warp & 1;
  const int gr = lane >> 2, tg = lane & 3;
  const int rowA = blockIdx.y * 128, colB = blockIdx.x * 64;

  const unsigned* gAh = (const unsigned*)(EPI ? g_ah : g_xh);
  const unsigned* gAl = (const unsigned*)(EPI ? g_al : g_xl);
  const unsigned* gBh = (const unsigned*)(EPI ? g_pwh : g_wh);
  const unsigned* gBl = (const unsigned*)(EPI ? g_pwl : g_wl);

  const uint32_t sb0 = s2u(dynsm);
  const uint32_t aoff = ((wm*32 + (lane&7) + ((lane>>3)&1)*8)*20 + (lane>>4)*4)*4;
  const uint32_t boff = ((wn*32 + (lane&7) + (lane>>4)*8)*20 + ((lane>>3)&1)*4)*4;
  const int ar = tid >> 2, aq = (tid & 3) * 4;

  auto stage = [&](int c, int b) {
    uint32_t sb = sb0 + b*30720;
    uint32_t off = (ar*20 + aq)*4;
    CP16(sb + off,          gAh + (size_t)(rowA + ar)*384 + c*16 + aq);
    CP16(sb + 10240 + off,  gAl + (size_t)(rowA + ar)*384 + c*16 + aq);
    CP16(sb + off + 64*80,          gAh + (size_t)(rowA + 64 + ar)*384 + c*16 + aq);
    CP16(sb + 10240 + off + 64*80,  gAl + (size_t)(rowA + 64 + ar)*384 + c*16 + aq);
    CP16(sb + 20480 + off,  gBh + (size_t)(colB + ar)*384 + c*16 + aq);
    CP16(sb + 25600 + off,  gBl + (size_t)(colB + ar)*384 + c*16 + aq);
  };

  float acc[2][4][4];
  #pragma unroll
  for (int m = 0; m < 2; m++)
    #pragma unroll
    for (int n = 0; n < 4; n++)
      #pragma unroll
      for (int e = 0; e < 4; e++) acc[m][n][e] = 0.f;

  stage(0, 0); CP_COMMIT;
  stage(1, 1); CP_COMMIT;
  for (int c = 0; c < 24; c++) {
    if (c < 23) { CP_WAIT1; } else { CP_WAIT0; }
    __syncthreads();
    if (c < 22) { stage(c+2, (c+2) % 3); CP_COMMIT; }
    const uint32_t sb = sb0 + (c % 3)*30720;
    #pragma unroll
    for (int ks = 0; ks < 2; ks++) {
      unsigned ah[2][4], al[2][4];
      LDSM4(ah[0], sb + aoff + ks*32);
      LDSM4(ah[1], sb + aoff + 1280 + ks*32);
      LDSM4(al[0], sb + 10240 + aoff + ks*32);
      LDSM4(al[1], sb + 10240 + aoff + 1280 + ks*32);
      #pragma unroll
      for (int p = 0; p < 2; p++) {
        unsigned bh4[4], bl4[4];
        LDSM4(bh4, sb + 20480 + boff + p*1280 + ks*32);
        LDSM4(bl4, sb + 25600 + boff + p*1280 + ks*32);
        #pragma unroll
        for (int h = 0; h < 2; h++) {
          const int nt = 2*p + h;
          unsigned bh2[2] = { bh4[2*h], bh4[2*h+1] };
          unsigned bl2[2] = { bl4[2*h], bl4[2*h+1] };
          #pragma unroll
          for (int mt = 0; mt < 2; mt++) {
            mma16816(acc[mt][nt], ah[mt], bh2);
            mma16816(acc[mt][nt], ah[mt], bl2);
            mma16816(acc[mt][nt], al[mt], bh2);
          }
        }
      }
    }
    __syncthreads();
  }

  if (EPI == 0) {
    const int which = colB / DIM, head = (colB % DIM) / HD;
    #pragma unroll
    for (int mt = 0; mt < 2; mt++) {
      int r = rowA + wm*32 + mt*16 + gr;
      int b = r >> 10, n = r & 1023;
      size_t bhh = (size_t)(b*HEADS + head);
      #pragma unroll
      for (int nt = 0; nt < 4; nt++) {
        int d0 = wn*32 + nt*8 + tg*2;
        float b0 = bias[colB+d0], b1 = bias[colB+d0+1];
        float v0 = acc[mt][nt][0]+b0, v1 = acc[mt][nt][1]+b1;
        float v2 = acc[mt][nt][2]+b0, v3 = acc[mt][nt][3]+b1;
        float h0 = bf16hi(v0), h1 = bf16hi(v1), h2 = bf16hi(v2), h3 = bf16hi(v3);
        if (which == 2) {
          size_t a0 = (bhh*HD + d0)*NTOK + n, a1 = a0 + NTOK;
          g_vth[a0]   = __float2bfloat16(h0); g_vtl[a0]   = __float2bfloat16(v0-h0);
          g_vth[a1]   = __float2bfloat16(h1); g_vtl[a1]   = __float2bfloat16(v1-h1);
          g_vth[a0+8] = __float2bfloat16(h2); g_vtl[a0+8] = __float2bfloat16(v2-h2);
          g_vth[a1+8] = __float2bfloat16(h3); g_vtl[a1+8] = __float2bfloat16(v3-h3);
        } else {
          __nv_bfloat16* dh = which ? g_kh : g_qh;
          __nv_bfloat16* dl = which ? g_kl : g_ql;
          size_t base = (bhh * NTOK + n) * HD;
          *(unsigned*)&dh[base+d0]      = pack2(h0, h1);
          *(unsigned*)&dl[base+d0]      = pack2(v0-h0, v1-h1);
          *(unsigned*)&dh[base+8*HD+d0] = pack2(h2, h3);
          *(unsigned*)&dl[base+8*HD+d0] = pack2(v2-h2, v3-h3);
        }
      }
    }
  } else {
    #pragma unroll
    for (int mt = 0; mt < 2; mt++) {
      int r = rowA + wm*32 + mt*16 + gr;
      #pragma unroll
      for (int nt = 0; nt < 4; nt++) {
        int c0 = colB + wn*32 + nt*8 + tg*2;
        float b0 = bias[c0], b1 = bias[c0+1];
        float2 v;
        v.x = acc[mt][nt][0]+b0; v.y = acc[mt][nt][1]+b1;
        *(float2*)&out[(size_t)r*DIM + c0] = v;
        v.x = acc[mt][nt][2]+b0; v.y = acc[mt][nt][3]+b1;
        *(float2*)&out[(size_t)(r+8)*DIM + c0] = v;
      }
    }
  }
}

// rel-pos (unchanged)
__global__ __launch_bounds__(256) void relpos_kernel(
    const float* __restrict__ rph, const float* __restrict__ rpw) {
  extern __shared__ float rsm[];
  float* sq = rsm;
  float* sH = sq + 64*64;
  float* sW = sH + 63*65;
  const int bh = blockIdx.y, n0 = blockIdx.x * 64, tid = threadIdx.x;
  for (int i = tid; i < 63*64; i += 256) {
    int r = i >> 6, c = i & 63;
    sH[r*65 + c] = rph[i];
    sW[r*65 + c] = rpw[i];
  }
  {
    size_t base = ((size_t)bh * NTOK + n0) * HD;
    for (int i = tid; i < 64*64; i += 256)
      sq[i] = __bfloat162float(g_qh[base + i]) + __bfloat162float(g_ql[base + i]);
  }
  __syncthreads();
  const int tok = tid >> 2, part = tid & 3;
  const int n = n0 + tok, qh = n >> 5, qw = n & 31;
  const float* qrow = sq + tok * 64;
  #pragma unroll
  for (int i = 0; i < 16; i++) {
    const int idx = part * 16 + i;
    const float* trow; float* o;
    if (idx < 32) {
      trow = sH + (qh - idx + 31) * 65;
      o = &g_relh[((size_t)bh*NTOK + n)*32 + idx];
    } else {
      const int kw = idx - 32;
      trow = sW + (qw - kw + 31) * 65;
      o = &g_relw[((size_t)bh*NTOK + n)*32 + kw];
    }
    float a = 0.f;
    #pragma unroll
    for (int c = 0; c < 64; c++) a += qrow[c] * trow[c];
    *o = a;
  }
}

// fused attention (R13 exactly): grid(8,96), 256 thr = 8 warps, warp = 16 q rows.
// Q frags in registers; K/V double-buffered cp.async; kk-outer S (8 accumulators
// for ILP), softmax/PV interleaved per j16.
__global__ __launch_bounds__(256, 2) void attn_kernel() {
  extern __shared__ unsigned sm[];
  float* sRh = (float*)(sm + 18432);
  float* sRw = sRh + 4224;

  const int bh = blockIdx.y, qt = blockIdx.x, tid = threadIdx.x;
  const int lane = tid & 31, wq = tid >> 5;
  const int gr = lane >> 2, tg = lane & 3;
  const int rq0 = wq*16 + gr;

  const uint32_t aoffQ = ((wq*16 + (lane&7) + ((lane>>3)&1)*8)*36 + (lane>>4)*4)*4;
  const uint32_t boffB = (((lane&7) + (lane>>4)*8)*36 + ((lane>>3)&1)*4)*4;
  const uint32_t uB0 = s2u(sm), uB1 = uB0 + 36864;

  {
    const unsigned* gQh = (const unsigned*)g_qh;
    const unsigned* gQl = (const unsigned*)g_ql;
    size_t qb = ((size_t)bh*NTOK + qt*128) * 32;
    #pragma unroll
    for (int i = tid; i < 4096; i += 256) {
      int r = i >> 5, c = i & 31;
      sm[r*36+c]        = gQh[qb+i];
      sm[4608 + r*36+c] = gQl[qb+i];
      sRh[r*33+c] = g_relh[qb+i];
      sRw[r*33+c] = g_relw[qb+i];
    }
  }
  __syncthreads();
  unsigned qa_h[4][4], qa_l[4][4];
  #pragma unroll
  for (int kk = 0; kk < 4; kk++) {
    LDSM4(qa_h[kk], uB0 + aoffQ + kk*32);
    LDSM4(qa_l[kk], uB0 + 18432 + aoffQ + kk*32);
  }
  __syncthreads();

  const unsigned* gKh = (const unsigned*)g_kh;
  const unsigned* gKl = (const unsigned*)g_kl;
  const unsigned* gVh = (const unsigned*)g_vth;
  const unsigned* gVl = (const unsigned*)g_vtl;
  const int r0 = tid >> 3, cq = (tid & 7) * 4;

  auto stage = [&](int kt, uint32_t uB) {
    size_t kb = ((size_t)bh*NTOK + kt*64) * 32;
    size_t vb = (size_t)bh*HD*512 + kt*32;
    #pragma unroll
    for (int ps = 0; ps < 2; ps++) {
      int r = ps*32 + r0;
      uint32_t dK = uB + (r*36 + cq)*4;
      CP16(dK,        gKh + kb + r*32 + cq);
      CP16(dK + 9216, gKl + kb + r*32 + cq);
      uint32_t dV = uB + 18432 + (r*36 + cq)*4;
      CP16(dV,        gVh + vb + (size_t)r*512 + cq);
      CP16(dV + 9216, gVl + vb + (size_t)r*512 + cq);
    }
    CP_COMMIT;
  };

  float oacc[8][4];
  #pragma unroll
  for (int n = 0; n < 8; n++)
    #pragma unroll
    for (int e = 0; e < 4; e++) oacc[n][e] = 0.f;
  float rs0 = 0.f, rs1 = 0.f;

  stage(0, uB0);
  for (int kt = 0; kt < 16; kt++) {
    CP_WAIT0;
    __syncthreads();
    const uint32_t uB = (kt & 1) ? uB1 : uB0;
    if (kt < 15) stage(kt+1, (kt & 1) ? uB0 : uB1);

    float sacc[8][4];
    #pragma unroll
    for (int j = 0; j < 8; j++)
      #pragma unroll
      for (int e = 0; e < 4; e++) sacc[j][e] = 0.f;

    #pragma unroll
    for (int kk = 0; kk < 4; kk++) {
      #pragma unroll
      for (int p = 0; p < 4; p++) {
        unsigned kh4[4], kl4[4];
        LDSM4(kh4, uB + boffB + p*2304 + kk*32);
        LDSM4(kl4, uB + 9216 + boffB + p*2304 + kk*32);
        #pragma unroll
        for (int h = 0; h < 2; h++) {
          const int j = 2*p + h;
          unsigned b2[2] = { kh4[2*h], kh4[2*h+1] };
          unsigned l2[2] = { kl4[2*h], kl4[2*h+1] };
          mma16816(sacc[j], qa_h[kk], b2);
          mma16816(sacc[j], qa_h[kk], l2);
          mma16816(sacc[j], qa_l[kk], b2);
        }
      }
    }

    // softmax + PV interleaved per j16 (phi/plo live range = 8 regs)
    #pragma unroll
    for (int j16 = 0; j16 < 4; j16++) {
      unsigned ph[4], pl[4];
      #pragma unroll
      for (int hh = 0; hh < 2; hh++) {
        const int j = j16*2 + hh;
        int kh  = kt*2 + (j >> 2);
        int kw0 = (j & 3)*8 + tg*2;
        float rh0 = sRh[rq0*33+kh], rh1 = sRh[(rq0+8)*33+kh];
        float e0 = __expf(fmaf(0.125f, sacc[j][0], rh0 + sRw[rq0*33+kw0]));
        float e1 = __expf(fmaf(0.125f, sacc[j][1], rh0 + sRw[rq0*33+kw0+1]));
        float e2 = __expf(fmaf(0.125f, sacc[j][2], rh1 + sRw[(rq0+8)*33+kw0]));
        float e3 = __expf(fmaf(0.125f, sacc[j][3], rh1 + sRw[(rq0+8)*33+kw0+1]));
        rs0 += e0 + e1;
        rs1 += e2 + e3;
        float h0 = bf16hi(e0), h1 = bf16hi(e1), h2 = bf16hi(e2), h3 = bf16hi(e3);
        ph[hh*2]   = pack2(h0, h1);
        ph[hh*2+1] = pack2(h2, h3);
        pl[hh*2]   = pack2(e0-h0, e1-h1);
        pl[hh*2+1] = pack2(e2-h2, e3-h3);
      }
      #pragma unroll
      for (int p = 0; p < 4; p++) {
        unsigned vh4[4], vl4[4];
        LDSM4(vh4, uB + 18432 + boffB + p*2304 + j16*32);
        LDSM4(vl4, uB + 27648 + boffB + p*2304 + j16*32);
        #pragma unroll
        for (int hh = 0; hh < 2; hh++) {
          const int nt = 2*p + hh;
          unsigned b2[2] = { vh4[2*hh], vh4[2*hh+1] };
          unsigned l2[2] = { vl4[2*hh], vl4[2*hh+1] };
          mma16816(oacc[nt], ph, b2);
          mma16816(oacc[nt], ph, l2);
          mma16816(oacc[nt], pl, b2);
        }
      }
    }
  }

  rs0 += __shfl_xor_sync(0xffffffffu, rs0, 1);
  rs0 += __shfl_xor_sync(0xffffffffu, rs0, 2);
  rs1 += __shfl_xor_sync(0xffffffffu, rs1, 1);
  rs1 += __shfl_xor_sync(0xffffffffu, rs1, 2);
  const float inv0 = 1.f / rs0, inv1 = 1.f / rs1;

  const int b = bh / HEADS, head = bh % HEADS;
  const int n0 = qt*128 + wq*16 + gr;
  #pragma unroll
  for (int nt = 0; nt < 8; nt++) {
    int d0 = nt*8 + tg*2;
    float o0 = oacc[nt][0]*inv0, o1 = oacc[nt][1]*inv0;
    float o2 = oacc[nt][2]*inv1, o3 = oacc[nt][3]*inv1;
    size_t b0 = ((size_t)(b*NTOK) + n0)*DIM + head*HD + d0;
    size_t b1 = ((size_t)(b*NTOK) + n0 + 8)*DIM + head*HD + d0;
    float h0 = bf16hi(o0), h1 = bf16hi(o1), h2 = bf16hi(o2), h3 = bf16hi(o3);
    *(unsigned*)&g_ah[b0] = pack2(h0, h1);
    *(unsigned*)&g_al[b0] = pack2(o0-h0, o1-h1);
    *(unsigned*)&g_ah[b1] = pack2(h2, h3);
    *(unsigned*)&g_al[b1] = pack2(o2-h2, o3-h3);
  }
}

extern "C" void kernel_launch(void* const* d_in, const int* in_sizes, int n_in,
                              void* d_out, int out_size) {
  const float* x      = (const float*)d_in[0];
  const float* qkv_w  = (const float*)d_in[1];
  const float* qkv_b  = (const float*)d_in[2];
  const float* proj_w = (const float*)d_in[3];
  const float* proj_b = (const float*)d_in[4];
  const float* rph    = (const float*)d_in[5];
  const float* rpw    = (const float*)d_in[6];
  float* out = (float*)d_out;

  cudaFuncSetAttribute(attn_kernel, cudaFuncAttributeMaxDynamicSharedMemorySize, 107520);
  cudaFuncSetAttribute(relpos_kernel, cudaFuncAttributeMaxDynamicSharedMemorySize, 49152);
  cudaFuncSetAttribute(gemm3bf16<0>, cudaFuncAttributeMaxDynamicSharedMemorySize, 92160);
  cudaFuncSetAttribute(gemm3bf16<1>, cudaFuncAttributeMaxDynamicSharedMemorySize, 92160);

  split_all_kernel<<<(NX + NW + NP + 255)/256, 256>>>(x, qkv_w, proj_w);

  gemm3bf16<0><<<dim3(36, 64), 256, 92160>>>(qkv_b, nullptr);
  relpos_kernel<<<dim3(16, 96), 256, 49152>>>(rph, rpw);
  attn_kernel<<<dim3(8, 96), 256, 107520>>>();
  gemm3bf16<1><<<dim3(12, 64), 256, 92160>>>(proj_b, out);
}

// round 16
// speedup vs baseline: 1.0719x; 1.0719x over previous
#include <cuda_runtime.h>
#include <cuda_bf16.h>
#include <cstdint>

#define HEADS 12
#define NTOK  1024
#define HD    64
#define DIM   768
#define BHT   96
#define MTOT  8192

__device__ __align__(16) __nv_bfloat16 g_xh[MTOT*DIM],  g_xl[MTOT*DIM];
__device__ __align__(16) __nv_bfloat16 g_wh[2304*DIM],  g_wl[2304*DIM];
__device__ __align__(16) __nv_bfloat16 g_pwh[DIM*DIM],  g_pwl[DIM*DIM];
__device__ __align__(16) __nv_bfloat16 g_qh[BHT*NTOK*HD], g_ql[BHT*NTOK*HD];
__device__ __align__(16) __nv_bfloat16 g_kh[BHT*NTOK*HD], g_kl[BHT*NTOK*HD];
__device__ __align__(16) __nv_bfloat16 g_vth[BHT*HD*NTOK], g_vtl[BHT*HD*NTOK];
__device__ __align__(16) __nv_bfloat16 g_ah[MTOT*DIM],  g_al[MTOT*DIM];
__device__ float g_relh[BHT*NTOK*32];
__device__ float g_relw[BHT*NTOK*32];

__device__ __forceinline__ void mma16816(float* c, const unsigned* a, const unsigned* b) {
  asm volatile(
    "mma.sync.aligned.m16n8k16.row.col.f32.bf16.bf16.f32 "
    "{%0,%1,%2,%3}, {%4,%5,%6,%7}, {%8,%9}, {%0,%1,%2,%3};\n"
    : "+f"(c[0]), "+f"(c[1]), "+f"(c[2]), "+f"(c[3])
    : "r"(a[0]), "r"(a[1]), "r"(a[2]), "r"(a[3]), "r"(b[0]), "r"(b[1]));
}
__device__ __forceinline__ unsigned pack2(float a, float b) {
  __nv_bfloat162 t = __floats2bfloat162_rn(a, b);
  return *reinterpret_cast<unsigned*>(&t);
}
__device__ __forceinline__ float bf16hi(float v) {
  return __bfloat162float(__float2bfloat16(v));
}
__device__ __forceinline__ uint32_t s2u(const void* p) {
  uint32_t a;
  asm("{ .reg .u64 t; cvta.to.shared.u64 t, %1; cvt.u32.u64 %0, t; }" : "=r"(a) : "l"(p));
  return a;
}
#define LDSM4(r, a) \
  asm volatile("ldmatrix.sync.aligned.m8n8.x4.shared.b16 {%0,%1,%2,%3},[%4];" \
    : "=r"((r)[0]), "=r"((r)[1]), "=r"((r)[2]), "=r"((r)[3]) : "r"(a))
#define CP16(s, g) \
  asm volatile("cp.async.cg.shared.global [%0],[%1],16;" :: "r"(s), "l"(g))
#define CP_COMMIT asm volatile("cp.async.commit_group;" ::: "memory")
#define CP_WAIT1  asm volatile("cp.async.wait_group 1;" ::: "memory")
#define CP_WAIT0  asm volatile("cp.async.wait_group 0;" ::: "memory")

#define NX (MTOT*DIM)
#define NW (2304*DIM)
#define NP (DIM*DIM)

// merged fp32 -> bf16 hi/lo split for x, qkv_w, proj_w in one launch
__global__ void split_all_kernel(const float* __restrict__ x,
                                 const float* __restrict__ w,
                                 const float* __restrict__ pw) {
  int i = blockIdx.x * 256 + threadIdx.x;
  const float* src;
  __nv_bfloat16 *h, *l;
  int j;
  if (i < NX)           { src = x;  h = g_xh;  l = g_xl;  j = i; }
  else if (i < NX+NW)   { src = w;  h = g_wh;  l = g_wl;  j = i - NX; }
  else if (i < NX+NW+NP){ src = pw; h = g_pwh; l = g_pwl; j = i - NX - NW; }
  else return;
  float v = src[j];
  __nv_bfloat16 hb = __float2bfloat16(v);
  h[j] = hb;
  l[j] = __float2bfloat16(v - __bfloat162float(hb));
}

// GEMM (R13 schedule exactly): tile 128x64, 3-stage cp.async, 24 K-chunks of 32,
// stage(c+2) issued after compute body, single top barrier.
template<int EPI>
__global__ __launch_bounds__(256, 2) void gemm3bf16(const float* __restrict__ bias,
                                                    float* __restrict__ out) {
  extern __shared__ __align__(16) unsigned dynsm[];
  const int tid = threadIdx.x, lane = tid & 31, warp = tid >> 5;
  const int wm = warp >> 1, wn = warp & 1;
  const int gr = lane >> 2, tg = lane & 3;
  const int rowA = blockIdx.y * 128, colB = blockIdx.x * 64;

  const unsigned* gAh = (const unsigned*)(EPI ? g_ah : g_xh);
  const unsigned* gAl = (const unsigned*)(EPI ? g_al : g_xl);
  const unsigned* gBh = (const unsigned*)(EPI ? g_pwh : g_wh);
  const unsigned* gBl = (const unsigned*)(EPI ? g_pwl : g_wl);

  const uint32_t sb0 = s2u(dynsm);
  const uint32_t aoff = ((wm*32 + (lane&7) + ((lane>>3)&1)*8)*20 + (lane>>4)*4)*4;
  const uint32_t boff = ((wn*32 + (lane&7) + (lane>>4)*8)*20 + ((lane>>3)&1)*4)*4;
  const int ar = tid >> 2, aq = (tid & 3) * 4;

  auto stage = [&](int c, int b) {
    uint32_t sb = sb0 + b*30720;
    uint32_t off = (ar*20 + aq)*4;
    CP16(sb + off,          gAh + (size_t)(rowA + ar)*384 + c*16 + aq);
    CP16(sb + 10240 + off,  gAl + (size_t)(rowA + ar)*384 + c*16 + aq);
    CP16(sb + off + 64*80,          gAh + (size_t)(rowA + 64 + ar)*384 + c*16 + aq);
    CP16(sb + 10240 + off + 64*80,  gAl + (size_t)(rowA + 64 + ar)*384 + c*16 + aq);
    CP16(sb + 20480 + off,  gBh + (size_t)(colB + ar)*384 + c*16 + aq);
    CP16(sb + 25600 + off,  gBl + (size_t)(colB + ar)*384 + c*16 + aq);
  };

  float acc[2][4][4];
  #pragma unroll
  for (int m = 0; m < 2; m++)
    #pragma unroll
    for (int n = 0; n < 4; n++)
      #pragma unroll
      for (int e = 0; e < 4; e++) acc[m][n][e] = 0.f;

  stage(0, 0); CP_COMMIT;
  stage(1, 1); CP_COMMIT;
  for (int c = 0; c < 24; c++) {
    if (c < 23) { CP_WAIT1; } else { CP_WAIT0; }
    __syncthreads();
    const uint32_t sb = sb0 + (c % 3)*30720;
    #pragma unroll
    for (int ks = 0; ks < 2; ks++) {
      unsigned ah[2][4], al[2][4];
      LDSM4(ah[0], sb + aoff + ks*32);
      LDSM4(ah[1], sb + aoff + 1280 + ks*32);
      LDSM4(al[0], sb + 10240 + aoff + ks*32);
      LDSM4(al[1], sb + 10240 + aoff + 1280 + ks*32);
      #pragma unroll
      for (int p = 0; p < 2; p++) {
        unsigned bh4[4], bl4[4];
        LDSM4(bh4, sb + 20480 + boff + p*1280 + ks*32);
        LDSM4(bl4, sb + 25600 + boff + p*1280 + ks*32);
        #pragma unroll
        for (int h = 0; h < 2; h++) {
          const int nt = 2*p + h;
          unsigned bh2[2] = { bh4[2*h], bh4[2*h+1] };
          unsigned bl2[2] = { bl4[2*h], bl4[2*h+1] };
          #pragma unroll
          for (int mt = 0; mt < 2; mt++) {
            mma16816(acc[mt][nt], ah[mt], bh2);
            mma16816(acc[mt][nt], ah[mt], bl2);
            mma16816(acc[mt][nt], al[mt], bh2);
          }
        }
      }
    }
    if (c < 22) { stage(c+2, (c+2) % 3); CP_COMMIT; }
  }

  if (EPI == 0) {
    const int which = colB / DIM, head = (colB % DIM) / HD;
    #pragma unroll
    for (int mt = 0; mt < 2; mt++) {
      int r = rowA + wm*32 + mt*16 + gr;
      int b = r >> 10, n = r & 1023;
      size_t bhh = (size_t)(b*HEADS + head);
      #pragma unroll
      for (int nt = 0; nt < 4; nt++) {
        int d0 = wn*32 + nt*8 + tg*2;
        float b0 = bias[colB+d0], b1 = bias[colB+d0+1];
        float v0 = acc[mt][nt][0]+b0, v1 = acc[mt][nt][1]+b1;
        float v2 = acc[mt][nt][2]+b0, v3 = acc[mt][nt][3]+b1;
        float h0 = bf16hi(v0), h1 = bf16hi(v1), h2 = bf16hi(v2), h3 = bf16hi(v3);
        if (which == 2) {
          size_t a0 = (bhh*HD + d0)*NTOK + n, a1 = a0 + NTOK;
          g_vth[a0]   = __float2bfloat16(h0); g_vtl[a0]   = __float2bfloat16(v0-h0);
          g_vth[a1]   = __float2bfloat16(h1); g_vtl[a1]   = __float2bfloat16(v1-h1);
          g_vth[a0+8] = __float2bfloat16(h2); g_vtl[a0+8] = __float2bfloat16(v2-h2);
          g_vth[a1+8] = __float2bfloat16(h3); g_vtl[a1+8] = __float2bfloat16(v3-h3);
        } else {
          __nv_bfloat16* dh = which ? g_kh : g_qh;
          __nv_bfloat16* dl = which ? g_kl : g_ql;
          size_t base = (bhh * NTOK + n) * HD;
          *(unsigned*)&dh[base+d0]      = pack2(h0, h1);
          *(unsigned*)&dl[base+d0]      = pack2(v0-h0, v1-h1);
          *(unsigned*)&dh[base+8*HD+d0] = pack2(h2, h3);
          *(unsigned*)&dl[base+8*HD+d0] = pack2(v2-h2, v3-h3);
        }
      }
    }
  } else {
    #pragma unroll
    for (int mt = 0; mt < 2; mt++) {
      int r = rowA + wm*32 + mt*16 + gr;
      #pragma unroll
      for (int nt = 0; nt < 4; nt++) {
        int c0 = colB + wn*32 + nt*8 + tg*2;
        float b0 = bias[c0], b1 = bias[c0+1];
        float2 v;
        v.x = acc[mt][nt][0]+b0; v.y = acc[mt][nt][1]+b1;
        *(float2*)&out[(size_t)r*DIM + c0] = v;
        v.x = acc[mt][nt][2]+b0; v.y = acc[mt][nt][3]+b1;
        *(float2*)&out[(size_t)(r+8)*DIM + c0] = v;
      }
    }
  }
}

// rel-pos: smem-cached tables; q padded to stride 65 (conflict-free reads).
// dyn smem: 64*65 + 2*63*65 floats = 49400 B.
__global__ __launch_bounds__(256) void relpos_kernel(
    const float* __restrict__ rph, const float* __restrict__ rpw) {
  extern __shared__ float rsm[];
  float* sq = rsm;             // [64][65]
  float* sH = sq + 64*65;      // [63][65]
  float* sW = sH + 63*65;      // [63][65]
  const int bh = blockIdx.y, n0 = blockIdx.x * 64, tid = threadIdx.x;
  for (int i = tid; i < 63*64; i += 256) {
    int r = i >> 6, c = i & 63;
    sH[r*65 + c] = rph[i];
    sW[r*65 + c] = rpw[i];
  }
  {
    size_t base = ((size_t)bh * NTOK + n0) * HD;
    for (int i = tid; i < 64*64; i += 256) {
      int r = i >> 6, c = i & 63;
      sq[r*65 + c] = __bfloat162float(g_qh[base + i]) + __bfloat162float(g_ql[base + i]);
    }
  }
  __syncthreads();
  const int tok = tid >> 2, part = tid & 3;
  const int n = n0 + tok, qh = n >> 5, qw = n & 31;
  const float* qrow = sq + tok * 65;
  #pragma unroll
  for (int i = 0; i < 16; i++) {
    const int idx = part * 16 + i;
    const float* trow; float* o;
    if (idx < 32) {
      trow = sH + (qh - idx + 31) * 65;
      o = &g_relh[((size_t)bh*NTOK + n)*32 + idx];
    } else {
      const int kw = idx - 32;
      trow = sW + (qw - kw + 31) * 65;
      o = &g_relw[((size_t)bh*NTOK + n)*32 + kw];
    }
    float a = 0.f;
    #pragma unroll
    for (int c = 0; c < 64; c++) a += qrow[c] * trow[c];
    *o = a;
  }
}

// fused attention (R13 exactly)
__global__ __launch_bounds__(256, 2) void attn_kernel() {
  extern __shared__ unsigned sm[];
  float* sRh = (float*)(sm + 18432);
  float* sRw = sRh + 4224;

  const int bh = blockIdx.y, qt = blockIdx.x, tid = threadIdx.x;
  const int lane = tid & 31, wq = tid >> 5;
  const int gr = lane >> 2, tg = lane & 3;
  const int rq0 = wq*16 + gr;

  const uint32_t aoffQ = ((wq*16 + (lane&7) + ((lane>>3)&1)*8)*36 + (lane>>4)*4)*4;
  const uint32_t boffB = (((lane&7) + (lane>>4)*8)*36 + ((lane>>3)&1)*4)*4;
  const uint32_t uB0 = s2u(sm), uB1 = uB0 + 36864;

  {
    const unsigned* gQh = (const unsigned*)g_qh;
    const unsigned* gQl = (const unsigned*)g_ql;
    size_t qb = ((size_t)bh*NTOK + qt*128) * 32;
    #pragma unroll
    for (int i = tid; i < 4096; i += 256) {
      int r = i >> 5, c = i & 31;
      sm[r*36+c]        = gQh[qb+i];
      sm[4608 + r*36+c] = gQl[qb+i];
      sRh[r*33+c] = g_relh[qb+i];
      sRw[r*33+c] = g_relw[qb+i];
    }
  }
  __syncthreads();
  unsigned qa_h[4][4], qa_l[4][4];
  #pragma unroll
  for (int kk = 0; kk < 4; kk++) {
    LDSM4(qa_h[kk], uB0 + aoffQ + kk*32);
    LDSM4(qa_l[kk], uB0 + 18432 + aoffQ + kk*32);
  }
  __syncthreads();

  const unsigned* gKh = (const unsigned*)g_kh;
  const unsigned* gKl = (const unsigned*)g_kl;
  const unsigned* gVh = (const unsigned*)g_vth;
  const unsigned* gVl = (const unsigned*)g_vtl;
  const int r0 = tid >> 3, cq = (tid & 7) * 4;

  auto stage = [&](int kt, uint32_t uB) {
    size_t kb = ((size_t)bh*NTOK + kt*64) * 32;
    size_t vb = (size_t)bh*HD*512 + kt*32;
    #pragma unroll
    for (int ps = 0; ps < 2; ps++) {
      int r = ps*32 + r0;
      uint32_t dK = uB + (r*36 + cq)*4;
      CP16(dK,        gKh + kb + r*32 + cq);
      CP16(dK + 9216, gKl + kb + r*32 + cq);
      uint32_t dV = uB + 18432 + (r*36 + cq)*4;
      CP16(dV,        gVh + vb + (size_t)r*512 + cq);
      CP16(dV + 9216, gVl + vb + (size_t)r*512 + cq);
    }
    CP_COMMIT;
  };

  float oacc[8][4];
  #pragma unroll
  for (int n = 0; n < 8; n++)
    #pragma unroll
    for (int e = 0; e < 4; e++) oacc[n][e] = 0.f;
  float rs0 = 0.f, rs1 = 0.f;

  stage(0, uB0);
  for (int kt = 0; kt < 16; kt++) {
    CP_WAIT0;
    __syncthreads();
    const uint32_t uB = (kt & 1) ? uB1 : uB0;
    if (kt < 15) stage(kt+1, (kt & 1) ? uB0 : uB1);

    float sacc[8][4];
    #pragma unroll
    for (int j = 0; j < 8; j++)
      #pragma unroll
      for (int e = 0; e < 4; e++) sacc[j][e] = 0.f;

    #pragma unroll
    for (int kk = 0; kk < 4; kk++) {
      #pragma unroll
      for (int p = 0; p < 4; p++) {
        unsigned kh4[4], kl4[4];
        LDSM4(kh4, uB + boffB + p*2304 + kk*32);
        LDSM4(kl4, uB + 9216 + boffB + p*2304 + kk*32);
        #pragma unroll
        for (int h = 0; h < 2; h++) {
          const int j = 2*p + h;
          unsigned b2[2] = { kh4[2*h], kh4[2*h+1] };
          unsigned l2[2] = { kl4[2*h], kl4[2*h+1] };
          mma16816(sacc[j], qa_h[kk], b2);
          mma16816(sacc[j], qa_h[kk], l2);
          mma16816(sacc[j], qa_l[kk], b2);
        }
      }
    }

    #pragma unroll
    for (int j16 = 0; j16 < 4; j16++) {
      unsigned ph[4], pl[4];
      #pragma unroll
      for (int hh = 0; hh < 2; hh++) {
        const int j = j16*2 + hh;
        int kh  = kt*2 + (j >> 2);
        int kw0 = (j & 3)*8 + tg*2;
        float rh0 = sRh[rq0*33+kh], rh1 = sRh[(rq0+8)*33+kh];
        float e0 = __expf(fmaf(0.125f, sacc[j][0], rh0 + sRw[rq0*33+kw0]));
        float e1 = __expf(fmaf(0.125f, sacc[j][1], rh0 + sRw[rq0*33+kw0+1]));
        float e2 = __expf(fmaf(0.125f, sacc[j][2], rh1 + sRw[(rq0+8)*33+kw0]));
        float e3 = __expf(fmaf(0.125f, sacc[j][3], rh1 + sRw[(rq0+8)*33+kw0+1]));
        rs0 += e0 + e1;
        rs1 += e2 + e3;
        float h0 = bf16hi(e0), h1 = bf16hi(e1), h2 = bf16hi(e2), h3 = bf16hi(e3);
        ph[hh*2]   = pack2(h0, h1);
        ph[hh*2+1] = pack2(h2, h3);
        pl[hh*2]   = pack2(e0-h0, e1-h1);
        pl[hh*2+1] = pack2(e2-h2, e3-h3);
      }
      #pragma unroll
      for (int p = 0; p < 4; p++) {
        unsigned vh4[4], vl4[4];
        LDSM4(vh4, uB + 18432 + boffB + p*2304 + j16*32);
        LDSM4(vl4, uB + 27648 + boffB + p*2304 + j16*32);
        #pragma unroll
        for (int hh = 0; hh < 2; hh++) {
          const int nt = 2*p + hh;
          unsigned b2[2] = { vh4[2*hh], vh4[2*hh+1] };
          unsigned l2[2] = { vl4[2*hh], vl4[2*hh+1] };
          mma16816(oacc[nt], ph, b2);
          mma16816(oacc[nt], ph, l2);
          mma16816(oacc[nt], pl, b2);
        }
      }
    }
  }

  rs0 += __shfl_xor_sync(0xffffffffu, rs0, 1);
  rs0 += __shfl_xor_sync(0xffffffffu, rs0, 2);
  rs1 += __shfl_xor_sync(0xffffffffu, rs1, 1);
  rs1 += __shfl_xor_sync(0xffffffffu, rs1, 2);
  const float inv0 = 1.f / rs0, inv1 = 1.f / rs1;

  const int b = bh / HEADS, head = bh % HEADS;
  const int n0 = qt*128 + wq*16 + gr;
  #pragma unroll
  for (int nt = 0; nt < 8; nt++) {
    int d0 = nt*8 + tg*2;
    float o0 = oacc[nt][0]*inv0, o1 = oacc[nt][1]*inv0;
    float o2 = oacc[nt][2]*inv1, o3 = oacc[nt][3]*inv1;
    size_t b0 = ((size_t)(b*NTOK) + n0)*DIM + head*HD + d0;
    size_t b1 = ((size_t)(b*NTOK) + n0 + 8)*DIM + head*HD + d0;
    float h0 = bf16hi(o0), h1 = bf16hi(o1), h2 = bf16hi(o2), h3 = bf16hi(o3);
    *(unsigned*)&g_ah[b0] = pack2(h0, h1);
    *(unsigned*)&g_al[b0] = pack2(o0-h0, o1-h1);
    *(unsigned*)&g_ah[b1] = pack2(h2, h3);
    *(unsigned*)&g_al[b1] = pack2(o2-h2, o3-h3);
  }
}

extern "C" void kernel_launch(void* const* d_in, const int* in_sizes, int n_in,
                              void* d_out, int out_size) {
  const float* x      = (const float*)d_in[0];
  const float* qkv_w  = (const float*)d_in[1];
  const float* qkv_b  = (const float*)d_in[2];
  const float* proj_w = (const float*)d_in[3];
  const float* proj_b = (const float*)d_in[4];
  const float* rph    = (const float*)d_in[5];
  const float* rpw    = (const float*)d_in[6];
  float* out = (float*)d_out;

  cudaFuncSetAttribute(attn_kernel, cudaFuncAttributeMaxDynamicSharedMemorySize, 107520);
  cudaFuncSetAttribute(relpos_kernel, cudaFuncAttributeMaxDynamicSharedMemorySize, 49408);
  cudaFuncSetAttribute(gemm3bf16<0>, cudaFuncAttributeMaxDynamicSharedMemorySize, 92160);
  cudaFuncSetAttribute(gemm3bf16<1>, cudaFuncAttributeMaxDynamicSharedMemorySize, 92160);

  split_all_kernel<<<(NX + NW + NP + 255)/256, 256>>>(x, qkv_w, proj_w);

  gemm3bf16<0><<<dim3(36, 64), 256, 92160>>>(qkv_b, nullptr);
  relpos_kernel<<<dim3(16, 96), 256, 49408>>>(rph, rpw);
  attn_kernel<<<dim3(8, 96), 256, 107520>>>();
  gemm3bf16<1><<<dim3(12, 64), 256, 92160>>>(proj_b, out);
}